// round 6
// baseline (speedup 1.0000x reference)
#include <cuda_runtime.h>
#include <math.h>

#define BB 128
#define SS 256
#define HH 512

// ---------------- device scratch (no allocations allowed) -------------------
__device__ float g_rsWr[HH];            // rowsum(Wr)
__device__ float g_rsW[HH];             // rowsum(W)
__device__ float g_part[4][BB * SS];    // per-jblock logit partials
__device__ float g_Gt[SS * BB];         // softmax gates, (s, b)
__device__ float g_C[2][HH * BB];       // recurrent state, transposed (h, b)

// ---------------- f32x2 helpers ----------------------------------------------
__device__ __forceinline__ unsigned long long pk2(float x, float y) {
    unsigned long long r;
    asm("mov.b64 %0, {%1,%2};" : "=l"(r) : "f"(x), "f"(y));
    return r;
}
__device__ __forceinline__ void upk2(unsigned long long v, float& x, float& y) {
    asm("mov.b64 {%0,%1}, %2;" : "=f"(x), "=f"(y) : "l"(v));
}
__device__ __forceinline__ unsigned long long fma2_(unsigned long long a,
                                                    unsigned long long b,
                                                    unsigned long long c) {
    unsigned long long d;
    asm("fma.rn.f32x2 %0, %1, %2, %3;" : "=l"(d) : "l"(a), "l"(b), "l"(c));
    return d;
}
__device__ __forceinline__ unsigned long long add2_(unsigned long long a,
                                                    unsigned long long b) {
    unsigned long long d;
    asm("add.rn.f32x2 %0, %1, %2;" : "=l"(d) : "l"(a), "l"(b));
    return d;
}
__device__ __forceinline__ float tanh_approx(float x) {
    float y;
    asm("tanh.approx.f32 %0, %1;" : "=f"(y) : "f"(x));
    return y;
}

// ---------------- prep: rowsums of Wr and W ----------------------------------
__global__ void prep_kernel(const float* __restrict__ Wr, const float* __restrict__ W)
{
    int warp = threadIdx.x >> 5, lane = threadIdx.x & 31;
    int rowId = blockIdx.x * 8 + warp;               // 0..1023
    const float* src = (rowId < HH) ? Wr : W;
    int h = rowId & (HH - 1);
    const float4* s4 = reinterpret_cast<const float4*>(src + (size_t)h * HH);
    float s = 0.f;
    for (int i = lane; i < HH / 4; i += 32) {
        float4 v = s4[i];
        s += (v.x + v.y) + (v.z + v.w);
    }
#pragma unroll
    for (int o = 16; o > 0; o >>= 1) s += __shfl_xor_sync(0xffffffffu, s, o);
    if (lane == 0) {
        if (rowId < HH) g_rsWr[h] = s;
        else            g_rsW[h]  = s;
    }
}

// ---------------- gate MLP: fused z-build + GEMM (f32x2, 8x8) + tanh + dot ---
// grid (S/128, 512/128, B), 256 threads. 128x128 tile, K=2048 built on the fly.
__global__ void __launch_bounds__(256, 2) gate_kernel(
    const float* __restrict__ facts, const float* __restrict__ q,
    const float* __restrict__ m, const float* __restrict__ z1w,
    const float* __restrict__ z1b, const float* __restrict__ z2w)
{
    __shared__ float qs[HH], ms[HH];
    __shared__ float As[4][16][132];   // padded rows: kill 16-way STS conflicts
    __shared__ float Bs[16][128];

    int tid = threadIdx.x;
    int b  = blockIdx.z;
    int s0 = blockIdx.x * 128;
    int j0 = blockIdx.y * 128;

    for (int i = tid; i < HH; i += 256) {
        qs[i] = q[b * HH + i];
        ms[i] = m[b * HH + i];
    }

    int tx = tid & 15, ty = tid >> 4;     // tx: 8 j's, ty: 8 s's
    unsigned long long acc2[4][8];        // [s-pair][j]
#pragma unroll
    for (int i = 0; i < 4; i++)
#pragma unroll
        for (int j = 0; j < 8; j++) acc2[i][j] = 0ull;

    const float* fb = facts + ((size_t)b * SS + s0) * HH;

    for (int k0 = 0; k0 < HH; k0 += 16) {
        __syncthreads();   // prev compute done (also covers qs/ms on k0==0)
        for (int i = tid; i < 128 * 16; i += 256) {
            int ss = i >> 4, kk = i & 15;
            float fv = fb[(size_t)ss * HH + k0 + kk];
            float qv = qs[k0 + kk], mv = ms[k0 + kk];
            As[0][kk][ss] = fv * qv;
            As[1][kk][ss] = fv * mv;
            As[2][kk][ss] = fabsf(fv - qv);
            As[3][kk][ss] = fabsf(fv - mv);
        }
        for (int blk = 0; blk < 4; blk++) {
            __syncthreads();   // As ready / prev Bs consumed
            for (int i = tid; i < 16 * 128; i += 256) {
                int kk = i >> 7, jj = i & 127;
                Bs[kk][jj] = z1w[(size_t)(blk * HH + k0 + kk) * HH + j0 + jj];
            }
            __syncthreads();   // Bs ready
#pragma unroll
            for (int kk = 0; kk < 16; kk++) {
                ulonglong2 a01 = *reinterpret_cast<const ulonglong2*>(&As[blk][kk][ty * 8]);
                ulonglong2 a23 = *reinterpret_cast<const ulonglong2*>(&As[blk][kk][ty * 8 + 4]);
                float4 bv0 = *reinterpret_cast<const float4*>(&Bs[kk][tx * 8]);
                float4 bv1 = *reinterpret_cast<const float4*>(&Bs[kk][tx * 8 + 4]);
                unsigned long long ap[4] = {a01.x, a01.y, a23.x, a23.y};
                float bf[8] = {bv0.x, bv0.y, bv0.z, bv0.w, bv1.x, bv1.y, bv1.z, bv1.w};
#pragma unroll
                for (int j = 0; j < 8; j++) {
                    unsigned long long bd = pk2(bf[j], bf[j]);
#pragma unroll
                    for (int i = 0; i < 4; i++)
                        acc2[i][j] = fma2_(ap[i], bd, acc2[i][j]);
                }
            }
        }
    }

    // epilogue: tanh (approx), dot with z2_w, reduce over the 128 j's
    float z1bv[8], z2wv[8];
#pragma unroll
    for (int j = 0; j < 8; j++) {
        int jc = j0 + tx * 8 + j;
        z1bv[j] = z1b[jc];
        z2wv[j] = z2w[jc];
    }
    float p[8];
#pragma unroll
    for (int i = 0; i < 8; i++) p[i] = 0.f;
#pragma unroll
    for (int ip = 0; ip < 4; ip++) {
#pragma unroll
        for (int j = 0; j < 8; j++) {
            float lo, hi;
            upk2(acc2[ip][j], lo, hi);
            p[ip * 2 + 0] = fmaf(tanh_approx(lo + z1bv[j]), z2wv[j], p[ip * 2 + 0]);
            p[ip * 2 + 1] = fmaf(tanh_approx(hi + z1bv[j]), z2wv[j], p[ip * 2 + 1]);
        }
    }
#pragma unroll
    for (int i = 0; i < 8; i++) {
#pragma unroll
        for (int o = 8; o > 0; o >>= 1)
            p[i] += __shfl_xor_sync(0xffffffffu, p[i], o);
    }
    if (tx == 0) {
#pragma unroll
        for (int i = 0; i < 8; i++)
            g_part[blockIdx.y][b * SS + s0 + ty * 8 + i] = p[i];
    }
}

// ---------------- softmax over S per batch ------------------------------------
__global__ void softmax_kernel()
{
    int b = blockIdx.x, s = threadIdx.x;   // 256 threads
    float l = 0.f;
#pragma unroll
    for (int jb = 0; jb < 4; jb++) l += g_part[jb][b * SS + s];
    __shared__ float sm[256];
    sm[s] = l;
    __syncthreads();
#pragma unroll
    for (int o = 128; o > 0; o >>= 1) {
        if (s < o) sm[s] = fmaxf(sm[s], sm[s + o]);
        __syncthreads();
    }
    float mx = sm[0];
    __syncthreads();
    float e = expf(l - mx);
    sm[s] = e;
    __syncthreads();
#pragma unroll
    for (int o = 128; o > 0; o >>= 1) {
        if (s < o) sm[s] += sm[s + o];
        __syncthreads();
    }
    g_Gt[s * BB + b] = e / sm[0];
}

// ---------------- persistent scan: clusters of 16 h-group CTAs ----------------
// grid (16, 8): blockIdx.x = hg (cluster dim), blockIdx.y = bg (independent).
// Block owns 32 h x 16 b. Weights (128KB f32x2 h-pairs) persist in dyn smem;
// per step the 32KB C-slice is staged (duplicated) into smem. One cluster
// barrier per step replaces all global synchronization. Step 0 skips the GEMM
// entirely (C0 == 0).
__global__ void __launch_bounds__(512, 1) __cluster_dims__(16, 1, 1)
scan_persist(
    const float* __restrict__ facts,
    const float* __restrict__ Ur, const float* __restrict__ U,
    const float* __restrict__ br, const float* __restrict__ bur,
    const float* __restrict__ bw, const float* __restrict__ bu)
{
    extern __shared__ __align__(16) char dsm[];
    unsigned long long* wpk = reinterpret_cast<unsigned long long*>(dsm);           // [512][32]
    unsigned long long* Cs2 = reinterpret_cast<unsigned long long*>(dsm + 131072);  // [512][16]
    unsigned long long* red = Cs2;                                                  // alias [8][64][8]

    __shared__ unsigned long long fin[32][16];
    __shared__ float hcs[5][32];

    int tid = threadIdx.x;
    int hg = blockIdx.x;           // 0..15 (cluster rank)
    int bg = blockIdx.y;           // 0..7
    int h0 = hg * 32;
    int b0 = bg * 16;

    // one-time: pack weight slice (h-pairs for Ur at j<16, U at j>=16)
    for (int i = tid; i < 512 * 8; i += 512) {
        int k = i >> 3, qd = i & 7;
        float4 r4 = *reinterpret_cast<const float4*>(Ur + (size_t)k * HH + h0 + qd * 4);
        float4 u4 = *reinterpret_cast<const float4*>(U  + (size_t)k * HH + h0 + qd * 4);
        wpk[k * 32 + qd * 2]          = pk2(r4.x, r4.y);
        wpk[k * 32 + qd * 2 + 1]      = pk2(r4.z, r4.w);
        wpk[k * 32 + 16 + qd * 2]     = pk2(u4.x, u4.y);
        wpk[k * 32 + 16 + qd * 2 + 1] = pk2(u4.z, u4.w);
    }
    if (tid < 32) {
        int h = h0 + tid;
        hcs[0][tid] = g_rsWr[h];
        hcs[1][tid] = br[h] + bur[h];
        hcs[2][tid] = g_rsW[h];
        hcs[3][tid] = bw[h];
        hcs[4][tid] = bu[h];
    }
    __syncthreads();

    // compute mapping: thread = ks(8) x jq(8) x bp(8)
    int ks = tid >> 6;
    int jq = (tid >> 3) & 7;
    int bp = tid & 7;
    int slot = jq * 8 + bp;

    // epilogue mapping: thread = b(16) x h_local(32); warp spans h
    int eb  = tid >> 5;
    int ehl = tid & 31;
    float cur_c = 0.f;

    for (int s = 0; s < SS; s++) {
        float aR = 0.f, aU = 0.f;

        if (s > 0) {
            const float* __restrict__ Cin = g_C[s & 1];
            // stage C slice, duplicated for f32x2
            for (int i = tid; i < 512 * 16; i += 512) {
                int k = i >> 4, bl = i & 15;
                float c = __ldcg(Cin + (size_t)k * BB + b0 + bl);
                Cs2[k * 16 + bl] = pk2(c, c);
            }
            __syncthreads();

            unsigned long long acc[2][4];
#pragma unroll
            for (int i = 0; i < 2; i++)
#pragma unroll
                for (int j = 0; j < 4; j++) acc[i][j] = 0ull;

            int kb = ks * 64;
#pragma unroll 4
            for (int kk = 0; kk < 64; kk++) {
                int k = kb + kk;
                ulonglong2 cd = *reinterpret_cast<const ulonglong2*>(&Cs2[k * 16 + bp * 2]);
                ulonglong2 w0 = *reinterpret_cast<const ulonglong2*>(&wpk[k * 32 + jq * 4]);
                ulonglong2 w1 = *reinterpret_cast<const ulonglong2*>(&wpk[k * 32 + jq * 4 + 2]);
                acc[0][0] = fma2_(cd.x, w0.x, acc[0][0]);
                acc[0][1] = fma2_(cd.x, w0.y, acc[0][1]);
                acc[0][2] = fma2_(cd.x, w1.x, acc[0][2]);
                acc[0][3] = fma2_(cd.x, w1.y, acc[0][3]);
                acc[1][0] = fma2_(cd.y, w0.x, acc[1][0]);
                acc[1][1] = fma2_(cd.y, w0.y, acc[1][1]);
                acc[1][2] = fma2_(cd.y, w1.x, acc[1][2]);
                acc[1][3] = fma2_(cd.y, w1.y, acc[1][3]);
            }
            __syncthreads();   // Cs2 reads done before alias (red) writes

            unsigned long long* rp = &red[((size_t)ks * 64 + slot) * 8];
#pragma unroll
            for (int i = 0; i < 2; i++)
#pragma unroll
                for (int j = 0; j < 4; j++) rp[i * 4 + j] = acc[i][j];
            __syncthreads();

            // sum the 8 k-split partials -> fin[j][b]
            {
                int sl = tid >> 3, u = tid & 7;
                unsigned long long v = red[(size_t)sl * 8 + u];
#pragma unroll
                for (int k2 = 1; k2 < 8; k2++)
                    v = add2_(v, red[((size_t)k2 * 64 + sl) * 8 + u]);
                int bi = u >> 2, ji = u & 3;
                int jq2 = sl >> 3, bp2 = sl & 7;
                fin[jq2 * 4 + ji][bp2 * 2 + bi] = v;
            }
            __syncthreads();

            {
                int jp = ehl >> 1, half = ehl & 1;
                float r0, r1, u0, u1;
                upk2(fin[jp][eb], r0, r1);
                upk2(fin[16 + jp][eb], u0, u1);
                aR = half ? r1 : r0;
                aU = half ? u1 : u0;
            }
        }

        // epilogue: nonlinearity + blend; C kept in a register
        {
            float* __restrict__ Cout = g_C[(s + 1) & 1];
            int h = h0 + ehl, bglob = b0 + eb;
            float fv = __ldg(facts + ((size_t)bglob * SS + s) * HH + h);
            float g = g_Gt[s * BB + bglob];
            float rr = 1.f / (1.f + expf(-(fmaf(fv, hcs[0][ehl], hcs[1][ehl]) + aR)));
            float ht = tanhf(fmaf(rr, aU + hcs[4][ehl], fmaf(fv, hcs[2][ehl], hcs[3][ehl])));
            cur_c = fmaf(g, ht - cur_c, cur_c);
            Cout[(size_t)h * BB + bglob] = cur_c;
        }

        // cluster barrier: release C writes to the 15 peer CTAs, acquire theirs.
        asm volatile("barrier.cluster.arrive.aligned;" ::: "memory");
        asm volatile("barrier.cluster.wait.aligned;" ::: "memory");
    }
}

// ---------------- final: relu(concat @ nm_w + nm_b) ---------------------------
__global__ void __launch_bounds__(512) final_kernel(
    const float* __restrict__ prevM, const float* __restrict__ q,
    const float* __restrict__ nm_w, const float* __restrict__ nm_b,
    float* __restrict__ out)
{
    __shared__ float cs[3 * HH];
    int b = blockIdx.x, tid = threadIdx.x;    // 512 threads
    cs[tid]          = prevM[b * HH + tid];
    cs[HH + tid]     = g_C[0][(size_t)tid * BB + b];   // final C lives in buffer 0
    cs[2 * HH + tid] = q[b * HH + tid];
    __syncthreads();
    float acc = nm_b[tid];
#pragma unroll 8
    for (int k = 0; k < 3 * HH; k++)
        acc = fmaf(cs[k], nm_w[(size_t)k * HH + tid], acc);
    out[b * HH + tid] = fmaxf(acc, 0.f);
}

// ---------------- launch -------------------------------------------------------
extern "C" void kernel_launch(void* const* d_in, const int* in_sizes, int n_in,
                              void* d_out, int out_size)
{
    const float* facts     = (const float*)d_in[0];
    const float* questions = (const float*)d_in[1];
    const float* prevM     = (const float*)d_in[2];
    const float* z1_w      = (const float*)d_in[3];
    const float* z1_b      = (const float*)d_in[4];
    const float* z2_w      = (const float*)d_in[5];
    // d_in[6] z2_b: constant shift, softmax-invariant — unused
    const float* Wr        = (const float*)d_in[7];
    const float* br        = (const float*)d_in[8];
    const float* Ur        = (const float*)d_in[9];
    const float* bur       = (const float*)d_in[10];
    const float* W         = (const float*)d_in[11];
    const float* bw        = (const float*)d_in[12];
    const float* U         = (const float*)d_in[13];
    const float* bu        = (const float*)d_in[14];
    const float* nm_w      = (const float*)d_in[15];
    const float* nm_b      = (const float*)d_in[16];
    float* out = (float*)d_out;

    const int scan_smem = 131072 + 65536;   // wpk + Cs2/red = 192KB
    cudaFuncSetAttribute(scan_persist,
                         cudaFuncAttributeMaxDynamicSharedMemorySize, scan_smem);
    cudaFuncSetAttribute(scan_persist,
                         cudaFuncAttributeNonPortableClusterSizeAllowed, 1);

    prep_kernel<<<128, 256>>>(Wr, W);
    gate_kernel<<<dim3(2, 4, BB), 256>>>(facts, questions, prevM, z1_w, z1_b, z2_w);
    softmax_kernel<<<BB, 256>>>();
    scan_persist<<<dim3(16, 8), 512, scan_smem>>>(facts, Ur, U, br, bur, bw, bu);
    final_kernel<<<BB, 512>>>(prevM, questions, nm_w, nm_b, out);
}

// round 7
// speedup vs baseline: 1.8780x; 1.8780x over previous
#include <cuda_runtime.h>
#include <math.h>

#define BB 128
#define SS 256
#define HH 512

typedef unsigned long long u64;

// ---------------- device scratch (no allocations allowed) -------------------
__device__ float g_rsWr[HH];            // rowsum(Wr)
__device__ float g_rsW[HH];             // rowsum(W)
__device__ float g_part[4][BB * SS];    // per-jblock logit partials
__device__ float g_Gt[SS * BB];         // softmax gates, (s, b)
__device__ float g_C[2][HH * BB];       // recurrent state, transposed (h, b)
__device__ unsigned g_flags[8];         // per-bg step counters (zeroed by softmax)

// ---------------- f32x2 helpers ----------------------------------------------
__device__ __forceinline__ u64 pk2(float x, float y) {
    u64 r;
    asm("mov.b64 %0, {%1,%2};" : "=l"(r) : "f"(x), "f"(y));
    return r;
}
__device__ __forceinline__ void upk2(u64 v, float& x, float& y) {
    asm("mov.b64 {%0,%1}, %2;" : "=f"(x), "=f"(y) : "l"(v));
}
__device__ __forceinline__ u64 fma2_(u64 a, u64 b, u64 c) {
    u64 d;
    asm("fma.rn.f32x2 %0, %1, %2, %3;" : "=l"(d) : "l"(a), "l"(b), "l"(c));
    return d;
}
__device__ __forceinline__ u64 add2_(u64 a, u64 b) {
    u64 d;
    asm("add.rn.f32x2 %0, %1, %2;" : "=l"(d) : "l"(a), "l"(b));
    return d;
}
__device__ __forceinline__ float tanh_approx(float x) {
    float y;
    asm("tanh.approx.f32 %0, %1;" : "=f"(y) : "f"(x));
    return y;
}
__device__ __forceinline__ unsigned ld_acq(const unsigned* p) {
    unsigned v;
    asm volatile("ld.acquire.gpu.global.u32 %0, [%1];" : "=r"(v) : "l"(p));
    return v;
}

// ---------------- prep: rowsums of Wr and W ----------------------------------
__global__ void prep_kernel(const float* __restrict__ Wr, const float* __restrict__ W)
{
    int warp = threadIdx.x >> 5, lane = threadIdx.x & 31;
    int rowId = blockIdx.x * 8 + warp;               // 0..1023
    const float* src = (rowId < HH) ? Wr : W;
    int h = rowId & (HH - 1);
    const float4* s4 = reinterpret_cast<const float4*>(src + (size_t)h * HH);
    float s = 0.f;
    for (int i = lane; i < HH / 4; i += 32) {
        float4 v = s4[i];
        s += (v.x + v.y) + (v.z + v.w);
    }
#pragma unroll
    for (int o = 16; o > 0; o >>= 1) s += __shfl_xor_sync(0xffffffffu, s, o);
    if (lane == 0) {
        if (rowId < HH) g_rsWr[h] = s;
        else            g_rsW[h]  = s;
    }
}

// ---------------- gate MLP: fused z-build + GEMM (f32x2, 8x8) + tanh + dot ---
// grid (S/128, 512/128, B), 256 threads. 128x128 tile, K=2048 built on the fly.
__global__ void __launch_bounds__(256, 2) gate_kernel(
    const float* __restrict__ facts, const float* __restrict__ q,
    const float* __restrict__ m, const float* __restrict__ z1w,
    const float* __restrict__ z1b, const float* __restrict__ z2w)
{
    __shared__ float qs[HH], ms[HH];
    __shared__ float As[4][16][132];   // padded rows: kill 16-way STS conflicts
    __shared__ float Bs[16][128];

    int tid = threadIdx.x;
    int b  = blockIdx.z;
    int s0 = blockIdx.x * 128;
    int j0 = blockIdx.y * 128;

    for (int i = tid; i < HH; i += 256) {
        qs[i] = q[b * HH + i];
        ms[i] = m[b * HH + i];
    }

    int tx = tid & 15, ty = tid >> 4;     // tx: 8 j's, ty: 8 s's
    u64 acc2[4][8];                        // [s-pair][j]
#pragma unroll
    for (int i = 0; i < 4; i++)
#pragma unroll
        for (int j = 0; j < 8; j++) acc2[i][j] = 0ull;

    const float* fb = facts + ((size_t)b * SS + s0) * HH;

    for (int k0 = 0; k0 < HH; k0 += 16) {
        __syncthreads();   // prev compute done (also covers qs/ms on k0==0)
        for (int i = tid; i < 128 * 16; i += 256) {
            int ss = i >> 4, kk = i & 15;
            float fv = fb[(size_t)ss * HH + k0 + kk];
            float qv = qs[k0 + kk], mv = ms[k0 + kk];
            As[0][kk][ss] = fv * qv;
            As[1][kk][ss] = fv * mv;
            As[2][kk][ss] = fabsf(fv - qv);
            As[3][kk][ss] = fabsf(fv - mv);
        }
        for (int blk = 0; blk < 4; blk++) {
            __syncthreads();   // As ready / prev Bs consumed
            for (int i = tid; i < 16 * 128; i += 256) {
                int kk = i >> 7, jj = i & 127;
                Bs[kk][jj] = z1w[(size_t)(blk * HH + k0 + kk) * HH + j0 + jj];
            }
            __syncthreads();   // Bs ready
#pragma unroll
            for (int kk = 0; kk < 16; kk++) {
                ulonglong2 a01 = *reinterpret_cast<const ulonglong2*>(&As[blk][kk][ty * 8]);
                ulonglong2 a23 = *reinterpret_cast<const ulonglong2*>(&As[blk][kk][ty * 8 + 4]);
                float4 bv0 = *reinterpret_cast<const float4*>(&Bs[kk][tx * 8]);
                float4 bv1 = *reinterpret_cast<const float4*>(&Bs[kk][tx * 8 + 4]);
                u64 ap[4] = {a01.x, a01.y, a23.x, a23.y};
                float bf[8] = {bv0.x, bv0.y, bv0.z, bv0.w, bv1.x, bv1.y, bv1.z, bv1.w};
#pragma unroll
                for (int j = 0; j < 8; j++) {
                    u64 bd = pk2(bf[j], bf[j]);
#pragma unroll
                    for (int i = 0; i < 4; i++)
                        acc2[i][j] = fma2_(ap[i], bd, acc2[i][j]);
                }
            }
        }
    }

    // epilogue: tanh (approx), dot with z2_w, reduce over the 128 j's
    float z1bv[8], z2wv[8];
#pragma unroll
    for (int j = 0; j < 8; j++) {
        int jc = j0 + tx * 8 + j;
        z1bv[j] = z1b[jc];
        z2wv[j] = z2w[jc];
    }
    float p[8];
#pragma unroll
    for (int i = 0; i < 8; i++) p[i] = 0.f;
#pragma unroll
    for (int ip = 0; ip < 4; ip++) {
#pragma unroll
        for (int j = 0; j < 8; j++) {
            float lo, hi;
            upk2(acc2[ip][j], lo, hi);
            p[ip * 2 + 0] = fmaf(tanh_approx(lo + z1bv[j]), z2wv[j], p[ip * 2 + 0]);
            p[ip * 2 + 1] = fmaf(tanh_approx(hi + z1bv[j]), z2wv[j], p[ip * 2 + 1]);
        }
    }
#pragma unroll
    for (int i = 0; i < 8; i++) {
#pragma unroll
        for (int o = 8; o > 0; o >>= 1)
            p[i] += __shfl_xor_sync(0xffffffffu, p[i], o);
    }
    if (tx == 0) {
#pragma unroll
        for (int i = 0; i < 8; i++)
            g_part[blockIdx.y][b * SS + s0 + ty * 8 + i] = p[i];
    }
}

// ---------------- softmax over S per batch (also zeroes scan flags) -----------
__global__ void softmax_kernel()
{
    int b = blockIdx.x, s = threadIdx.x;   // 256 threads
    if (b == 0 && s < 8) g_flags[s] = 0u;  // stream-ordered before scan launch
    float l = 0.f;
#pragma unroll
    for (int jb = 0; jb < 4; jb++) l += g_part[jb][b * SS + s];
    __shared__ float sm[256];
    sm[s] = l;
    __syncthreads();
#pragma unroll
    for (int o = 128; o > 0; o >>= 1) {
        if (s < o) sm[s] = fmaxf(sm[s], sm[s + o]);
        __syncthreads();
    }
    float mx = sm[0];
    __syncthreads();
    float e = expf(l - mx);
    sm[s] = e;
    __syncthreads();
#pragma unroll
    for (int o = 128; o > 0; o >>= 1) {
        if (s < o) sm[s] += sm[s + o];
        __syncthreads();
    }
    g_Gt[s * BB + b] = e / sm[0];
}

// ---------------- persistent scan: 128 blocks = 16 hg x 8 bg ------------------
// Block owns 32 h x 16 b. Weights (R,U)-paired in smem (128KB) persist across
// all 256 steps. C is read straight from L2 (no staging). Per step: warp-level
// flag poll -> FMA-bound k-split GEMM -> 1 smem reduce -> fused epilogue.
// Thread (compute): tid = ks(16)*32 + hq(8)*4 + bq(4); tile 4h x 4b x {R,U}.
// Thread (reduce+epi): owns one (h,b): pos = tid>>4 (hq,bq), i = tid&15 (bb,hh).
__global__ void __launch_bounds__(512, 1) scan_persist(
    const float* __restrict__ facts,
    const float* __restrict__ Ur, const float* __restrict__ U,
    const float* __restrict__ br, const float* __restrict__ bur,
    const float* __restrict__ bw, const float* __restrict__ bu)
{
    extern __shared__ __align__(16) char dsm[];
    u64* wpk = reinterpret_cast<u64*>(dsm);            // [512][32]: pk2(Ur, U)
    u64* red = reinterpret_cast<u64*>(dsm + 131072);   // [16][16][33] padded

    __shared__ float hcs[5][32];

    int tid = threadIdx.x;
    int hg = blockIdx.x >> 3;      // 0..15
    int bg = blockIdx.x & 7;       // 0..7
    int h0 = hg * 32;
    int b0 = bg * 16;

    // one-time: pack (R,U) weight pairs for this h-slice
    for (int idx = tid; idx < 512 * 32; idx += 512) {
        int k = idx >> 5, h = idx & 31;
        wpk[idx] = pk2(Ur[(size_t)k * HH + h0 + h], U[(size_t)k * HH + h0 + h]);
    }
    if (tid < 32) {
        int h = h0 + tid;
        hcs[0][tid] = g_rsWr[h];
        hcs[1][tid] = br[h] + bur[h];
        hcs[2][tid] = g_rsW[h];
        hcs[3][tid] = bw[h];
        hcs[4][tid] = bu[h];
    }
    __syncthreads();

    // compute mapping
    int ks = tid >> 5;
    int lane = tid & 31;
    int hq = lane >> 2, bq = lane & 3;

    // reduce/epilogue mapping: one (h,b) per thread, fixed across steps
    int ep_pos = tid >> 4, ep_i = tid & 15;
    int e_hq = ep_pos >> 2, e_bq = ep_pos & 3;
    int e_hh = ep_i & 3,   e_bb = ep_i >> 2;        // hh fastest -> coalesced facts
    int ehl = e_hq * 4 + e_hh;                      // local h
    int eh  = h0 + ehl;
    int eb  = b0 + e_bq * 4 + e_bb;
    float cur_c = 0.f;

    for (int s = 0; s < SS; s++) {
        u64 aRU = 0ull;

        if (s > 0) {
            // warp-level poll: all 16 producers of this bg finished step s-1
            unsigned target = 16u * (unsigned)s;
            while (ld_acq(&g_flags[bg]) < target) {}

            const float* __restrict__ Cin = g_C[s & 1];
            u64 acc[4][4];
#pragma unroll
            for (int i = 0; i < 4; i++)
#pragma unroll
                for (int j = 0; j < 4; j++) acc[i][j] = 0ull;

            const float4* cp = reinterpret_cast<const float4*>(
                Cin + (size_t)(ks * 32) * BB + b0 + bq * 4);
#pragma unroll 4
            for (int kk = 0; kk < 32; kk++) {
                float4 cv = __ldcg(cp + (size_t)kk * (BB / 4));
                u64 cd[4] = {pk2(cv.x, cv.x), pk2(cv.y, cv.y),
                             pk2(cv.z, cv.z), pk2(cv.w, cv.w)};
                const u64* wr = &wpk[(ks * 32 + kk) * 32 + hq * 4];
                ulonglong2 w01 = *reinterpret_cast<const ulonglong2*>(wr);
                ulonglong2 w23 = *reinterpret_cast<const ulonglong2*>(wr + 2);
                u64 w[4] = {w01.x, w01.y, w23.x, w23.y};
#pragma unroll
                for (int hh = 0; hh < 4; hh++)
#pragma unroll
                    for (int bb = 0; bb < 4; bb++)
                        acc[hh][bb] = fma2_(cd[bb], w[hh], acc[hh][bb]);
            }

            // write k-split partials (prev step's red reads were sealed by the
            // arrival syncthreads of step s-1)
#pragma unroll
            for (int hh = 0; hh < 4; hh++)
#pragma unroll
                for (int bb = 0; bb < 4; bb++) {
                    int i = bb * 4 + hh;
                    red[(size_t)(ks * 16 + i) * 33 + lane] = acc[hh][bb];
                }
            __syncthreads();

            // each thread sums its 16 k-split partials for its own (h,b)
            u64 v = red[(size_t)ep_i * 33 + ep_pos];
#pragma unroll
            for (int t = 1; t < 16; t++)
                v = add2_(v, red[(size_t)(t * 16 + ep_i) * 33 + ep_pos]);
            aRU = v;
        }

        // fused epilogue: nonlinearity + blend; C kept in a register
        {
            float aR, aU;
            upk2(aRU, aR, aU);
            float* __restrict__ Cout = g_C[(s + 1) & 1];
            float fv = __ldg(facts + ((size_t)eb * SS + s) * HH + eh);
            float g = g_Gt[s * BB + eb];
            float rr = 1.f / (1.f + expf(-(fmaf(fv, hcs[0][ehl], hcs[1][ehl]) + aR)));
            float ht = tanhf(fmaf(rr, aU + hcs[4][ehl],
                                  fmaf(fv, hcs[2][ehl], hcs[3][ehl])));
            cur_c = fmaf(g, ht - cur_c, cur_c);
            Cout[(size_t)eh * BB + eb] = cur_c;
        }
        __threadfence();       // each thread makes its C store globally visible
        __syncthreads();       // all stores + fences done
        if (tid == 0) atomicAdd(&g_flags[bg], 1u);
    }
}

// ---------------- final: relu(concat @ nm_w + nm_b) ---------------------------
__global__ void __launch_bounds__(512) final_kernel(
    const float* __restrict__ prevM, const float* __restrict__ q,
    const float* __restrict__ nm_w, const float* __restrict__ nm_b,
    float* __restrict__ out)
{
    __shared__ float cs[3 * HH];
    int b = blockIdx.x, tid = threadIdx.x;    // 512 threads
    cs[tid]          = prevM[b * HH + tid];
    cs[HH + tid]     = g_C[0][(size_t)tid * BB + b];   // final C lives in buffer 0
    cs[2 * HH + tid] = q[b * HH + tid];
    __syncthreads();
    float acc = nm_b[tid];
#pragma unroll 8
    for (int k = 0; k < 3 * HH; k++)
        acc = fmaf(cs[k], nm_w[(size_t)k * HH + tid], acc);
    out[b * HH + tid] = fmaxf(acc, 0.f);
}

// ---------------- launch -------------------------------------------------------
extern "C" void kernel_launch(void* const* d_in, const int* in_sizes, int n_in,
                              void* d_out, int out_size)
{
    const float* facts     = (const float*)d_in[0];
    const float* questions = (const float*)d_in[1];
    const float* prevM     = (const float*)d_in[2];
    const float* z1_w      = (const float*)d_in[3];
    const float* z1_b      = (const float*)d_in[4];
    const float* z2_w      = (const float*)d_in[5];
    // d_in[6] z2_b: constant shift, softmax-invariant — unused
    const float* Wr        = (const float*)d_in[7];
    const float* br        = (const float*)d_in[8];
    const float* Ur        = (const float*)d_in[9];
    const float* bur       = (const float*)d_in[10];
    const float* W         = (const float*)d_in[11];
    const float* bw        = (const float*)d_in[12];
    const float* U         = (const float*)d_in[13];
    const float* bu        = (const float*)d_in[14];
    const float* nm_w      = (const float*)d_in[15];
    const float* nm_b      = (const float*)d_in[16];
    float* out = (float*)d_out;

    const int scan_smem = 131072 + 16 * 16 * 33 * 8;   // wpk + red = 198656
    cudaFuncSetAttribute(scan_persist,
                         cudaFuncAttributeMaxDynamicSharedMemorySize, scan_smem);

    prep_kernel<<<128, 256>>>(Wr, W);
    gate_kernel<<<dim3(2, 4, BB), 256>>>(facts, questions, prevM, z1_w, z1_b, z2_w);
    softmax_kernel<<<BB, 256>>>();
    scan_persist<<<128, 512, scan_smem>>>(facts, Ur, U, br, bur, bw, bu);
    final_kernel<<<BB, 512>>>(prevM, questions, nm_w, nm_b, out);
}